// round 2
// baseline (speedup 1.0000x reference)
#include <cuda_runtime.h>
#include <cstdint>

#define HID 512
#define BAT 32
#define TLEN 512
#define G4 2048
#define NBLK 128
#define NBLK_DIR 64
#define WP 68    // words per kp-row in Wt/ht (64 data + 4 pad, 16B-aligned)
#define RP 34    // words per row in reduction buffer

// ----------------------------------------------------------------------------
// Scratch (static __device__ — no allocations allowed)
// ----------------------------------------------------------------------------
__device__ float g_xg[2][TLEN][BAT][G4];       // 256 MB: xg[dir][t][b][gate]
__device__ float g_hbuf[2][2][BAT][HID];       // [parity][dir][b][j]
__device__ unsigned g_bar_cnt[2 * 32];         // [dir*32] — separate cache lines
__device__ volatile unsigned g_bar_gen[2 * 32];

// ----------------------------------------------------------------------------
// packed fp32x2 FMA (sm_100+): d = a*b + d elementwise on 2 packed floats
// ----------------------------------------------------------------------------
__device__ __forceinline__ void ffma2(unsigned long long& d,
                                      unsigned long long a,
                                      unsigned long long b)
{
    asm("fma.rn.f32x2 %0, %1, %2, %0;" : "+l"(d) : "l"(a), "l"(b));
}

__device__ __forceinline__ float lo32(unsigned long long v)
{
    return __uint_as_float((unsigned)(v & 0xffffffffull));
}
__device__ __forceinline__ float hi32(unsigned long long v)
{
    return __uint_as_float((unsigned)(v >> 32));
}

__device__ __forceinline__ float fsigmoid(float x)
{
    return 1.f / (1.f + __expf(-x));
}
__device__ __forceinline__ float ftanh(float x)
{
    float ax = fabsf(x);
    float e = __expf(2.f * ax);          // overflow -> inf -> t -> 1, fine
    float t = 1.f - 2.f / (e + 1.f);
    return copysignf(t, x);
}

// ----------------------------------------------------------------------------
// Kernel 1: xg[dir][t][b][g] = sum_k x[b][t][k] * Wih[g][k] + bih[g] + bhh[g]
// Classic 128x128x16 tiled SGEMM, both directions fused via blockIdx.z.
// ----------------------------------------------------------------------------
__global__ void __launch_bounds__(256) gemm_xg_kernel(
    const float* __restrict__ A,
    const float* __restrict__ Wf, const float* __restrict__ Wb,
    const float* __restrict__ bihf, const float* __restrict__ bhhf,
    const float* __restrict__ bihb, const float* __restrict__ bhhb)
{
    __shared__ float As[16][132];
    __shared__ float Bs[16][132];

    const int dir = blockIdx.z;
    const float* __restrict__ W   = dir ? Wb : Wf;
    const float* __restrict__ bih = dir ? bihb : bihf;
    const float* __restrict__ bhh = dir ? bhhb : bhhf;

    const int m0 = blockIdx.y * 128;
    const int n0 = blockIdx.x * 128;
    const int tid = threadIdx.x;
    const int tx = tid & 15;
    const int ty = tid >> 4;
    const int lrow = tid >> 2;          // 0..63
    const int lkc  = (tid & 3) * 4;     // 0,4,8,12

    float acc[8][8];
    #pragma unroll
    for (int i = 0; i < 8; i++)
        #pragma unroll
        for (int j = 0; j < 8; j++) acc[i][j] = 0.f;

    for (int k0 = 0; k0 < 512; k0 += 16) {
        #pragma unroll
        for (int u = 0; u < 2; u++) {
            int row = lrow + u * 64;
            float4 av = *(const float4*)&A[(size_t)(m0 + row) * 512 + k0 + lkc];
            As[lkc + 0][row] = av.x; As[lkc + 1][row] = av.y;
            As[lkc + 2][row] = av.z; As[lkc + 3][row] = av.w;
            float4 bv = *(const float4*)&W[(size_t)(n0 + row) * 512 + k0 + lkc];
            Bs[lkc + 0][row] = bv.x; Bs[lkc + 1][row] = bv.y;
            Bs[lkc + 2][row] = bv.z; Bs[lkc + 3][row] = bv.w;
        }
        __syncthreads();
        #pragma unroll
        for (int k = 0; k < 16; k++) {
            float a[8], b[8];
            *(float4*)&a[0] = *(const float4*)&As[k][ty * 8];
            *(float4*)&a[4] = *(const float4*)&As[k][ty * 8 + 4];
            *(float4*)&b[0] = *(const float4*)&Bs[k][tx * 8];
            *(float4*)&b[4] = *(const float4*)&Bs[k][tx * 8 + 4];
            #pragma unroll
            for (int i = 0; i < 8; i++)
                #pragma unroll
                for (int j = 0; j < 8; j++)
                    acc[i][j] = fmaf(a[i], b[j], acc[i][j]);
        }
        __syncthreads();
    }

    float bias[8];
    #pragma unroll
    for (int j = 0; j < 8; j++) {
        int n = n0 + tx * 8 + j;
        bias[j] = bih[n] + bhh[n];
    }
    #pragma unroll
    for (int i = 0; i < 8; i++) {
        int m = m0 + ty * 8 + i;
        int t = m & 511;
        int b = m >> 9;
        float* o = &g_xg[dir][t][b][n0 + tx * 8];
        float4 v0 = make_float4(acc[i][0] + bias[0], acc[i][1] + bias[1],
                                acc[i][2] + bias[2], acc[i][3] + bias[3]);
        float4 v1 = make_float4(acc[i][4] + bias[4], acc[i][5] + bias[5],
                                acc[i][6] + bias[6], acc[i][7] + bias[7]);
        *(float4*)&o[0] = v0;
        *(float4*)&o[4] = v1;
    }
}

// ----------------------------------------------------------------------------
// Per-direction, graph-replay-safe grid barrier (generation counting).
// 64 participating blocks per direction; all co-resident (1 block/SM by smem).
// ----------------------------------------------------------------------------
__device__ __forceinline__ void grid_barrier(int dir)
{
    __threadfence();
    __syncthreads();
    if (threadIdx.x == 0) {
        unsigned* cnt = &g_bar_cnt[dir * 32];
        volatile unsigned* gen = &g_bar_gen[dir * 32];
        unsigned g = *gen;
        unsigned ticket = atomicAdd(cnt, 1u);
        if (ticket == NBLK_DIR - 1u) {
            *cnt = 0u;
            __threadfence();
            *gen = g + 1u;
        } else {
            while (*gen == g) { }
        }
        __threadfence();
    }
    __syncthreads();
}

// ----------------------------------------------------------------------------
// Kernel 2: persistent scan. 128 blocks: dir = blk/64, hidden slice of 8 units
// (32 gate rows x 32 batches per step, K=512).
//
// smem layouts (k-PAIR packed for fp32x2):
//   Wt[kp][r*2 + p]  = Whh[gate*512+j0+jj][2kp+p],  r = gate*8 + jj, kp-row pitch WP
//   ht[kp][b*2 + p]  = h[b][2kp+p]
//   red[warp][rho][b], rho = jj*4 + gate, row pitch RP
//
// Matmul thread map: ks = tid>>4 (16-way k split), rg = gate group (rows),
//   bg = batch group; 8x8 register tile held as 64 packed f32x2 accumulators.
// Finalize map: fb = tid>>3 (batch), fj = tid&7 (hidden unit).
// ----------------------------------------------------------------------------
#define SMEM_FLOATS (2 * 256 * WP + 8 * 32 * RP)   // 43520 floats = 174080 B

__global__ void __launch_bounds__(256, 1) lstm_scan_kernel(
    const float* __restrict__ Whh_f,
    const float* __restrict__ Whh_b,
    float* __restrict__ out)
{
    extern __shared__ float sm[];
    float* Wt  = sm;                        // [256][WP]
    float* ht  = sm + 256 * WP;             // [256][WP]
    float* red = sm + 2 * 256 * WP;         // [8][32][RP]

    const int tid = threadIdx.x;
    const int dir = blockIdx.x >> 6;
    const int j0  = (blockIdx.x & 63) * 8;
    const float* __restrict__ Whh = dir ? Whh_b : Whh_f;

    // Load + transpose Whh slice into k-pair-packed Wt.
    {
        int r = tid & 31;                           // local row: gate*8 + jj
        int gr = (r >> 3) * 512 + j0 + (r & 7);
        const float* src = Whh + (size_t)gr * 512;
        int k0 = (tid >> 5) * 64;
        for (int k = k0; k < k0 + 64; k += 4) {
            float4 v = *(const float4*)&src[k];
            int kp = k >> 1;                        // even
            Wt[kp * WP + r * 2 + 0]       = v.x;
            Wt[kp * WP + r * 2 + 1]       = v.y;
            Wt[(kp + 1) * WP + r * 2 + 0] = v.z;
            Wt[(kp + 1) * WP + r * 2 + 1] = v.w;
        }
    }
    // h_{-1} = 0
    for (int i = tid; i < 256 * WP; i += 256) ht[i] = 0.f;

    const int ks = tid >> 4;          // 0..15  (k slice)
    const int w  = tid & 15;
    const int rg = w >> 2;            // 0..3   == gate
    const int bg = w & 3;             // 0..3   batch group
    const int warp = tid >> 5;        // 0..7
    const int fb = tid >> 3;          // 0..31  finalize batch
    const int fj = tid & 7;           // 0..7   finalize hidden unit
    float c_state = 0.f;

    const float* xg_base = &g_xg[dir][0][fb][j0 + fj];
    float* hb_base0 = &g_hbuf[0][dir][fb][j0 + fj];
    float* hb_base1 = &g_hbuf[1][dir][fb][j0 + fj];

    __syncthreads();

    for (int s = 0; s < 512; s++) {
        const int t = dir ? (511 - s) : s;

        // ---- prefetch xg for this thread's finalize cell (hidden under matmul)
        const float* xgp = xg_base + (size_t)t * (BAT * G4);
        float xi = xgp[0];
        float xf = xgp[512];
        float xgv = xgp[1024];
        float xo = xgp[1536];

        // ---- matmul: D[r][b] = sum_k Wt[k][r] * ht[k][b], packed over k pairs
        unsigned long long acc2[8][8];
        #pragma unroll
        for (int i = 0; i < 8; i++)
            #pragma unroll
            for (int j = 0; j < 8; j++) acc2[i][j] = 0ull;

        #pragma unroll 4
        for (int kk = 0; kk < 16; kk++) {
            int kp = kk * 16 + ks;
            unsigned long long a2[8], h2[8];
            {
                const ulonglong2* p = (const ulonglong2*)(Wt + kp * WP + (rg << 4));
                ulonglong2 v0 = p[0], v1 = p[1], v2 = p[2], v3 = p[3];
                a2[0] = v0.x; a2[1] = v0.y; a2[2] = v1.x; a2[3] = v1.y;
                a2[4] = v2.x; a2[5] = v2.y; a2[6] = v3.x; a2[7] = v3.y;
            }
            {
                const ulonglong2* p = (const ulonglong2*)(ht + kp * WP + (bg << 4));
                ulonglong2 v0 = p[0], v1 = p[1], v2 = p[2], v3 = p[3];
                h2[0] = v0.x; h2[1] = v0.y; h2[2] = v1.x; h2[3] = v1.y;
                h2[4] = v2.x; h2[5] = v2.y; h2[6] = v3.x; h2[7] = v3.y;
            }
            #pragma unroll
            for (int i = 0; i < 8; i++)
                #pragma unroll
                for (int j = 0; j < 8; j++)
                    ffma2(acc2[i][j], a2[i], h2[j]);
        }

        // ---- fold packed halves, then fold k-slice pairs across lane^16
        float accs[8][8];
        #pragma unroll
        for (int i = 0; i < 8; i++)
            #pragma unroll
            for (int j = 0; j < 8; j++) {
                float v = lo32(acc2[i][j]) + hi32(acc2[i][j]);
                accs[i][j] = v + __shfl_xor_sync(0xffffffffu, v, 16);
            }

        if ((tid & 16) == 0) {
            #pragma unroll
            for (int i = 0; i < 8; i++) {
                float* rp = red + warp * (32 * RP) + (i * 4 + rg) * RP + bg * 8;
                ((float2*)rp)[0] = make_float2(accs[i][0], accs[i][1]);
                ((float2*)rp)[1] = make_float2(accs[i][2], accs[i][3]);
                ((float2*)rp)[2] = make_float2(accs[i][4], accs[i][5]);
                ((float2*)rp)[3] = make_float2(accs[i][6], accs[i][7]);
            }
        }
        __syncthreads();

        // ---- finalize: thread (fb, fj) owns one (batch, hidden) cell
        {
            float d0 = 0.f, d1 = 0.f, d2 = 0.f, d3 = 0.f;
            #pragma unroll
            for (int wv = 0; wv < 8; wv++) {
                const float* rp = red + wv * (32 * RP) + fb;
                d0 += rp[(fj * 4 + 0) * RP];
                d1 += rp[(fj * 4 + 1) * RP];
                d2 += rp[(fj * 4 + 2) * RP];
                d3 += rp[(fj * 4 + 3) * RP];
            }
            float ig = fsigmoid(xi + d0);
            float fg = fsigmoid(xf + d1);
            float gg = ftanh(xgv + d2);
            float og = fsigmoid(xo + d3);
            c_state = fg * c_state + ig * gg;
            float hval = og * ftanh(c_state);

            out[(size_t)fb * (TLEN * 1024) + (size_t)t * 1024 + dir * 512 + j0 + fj] = hval;
            *((s & 1) ? hb_base1 : hb_base0) = hval;
        }

        if (s < 511) {
            grid_barrier(dir);
            // reload full h for this direction, transposed + k-pair packed
            int b  = tid & 31;
            int k0 = (tid >> 5) * 64;
            const float* src = &g_hbuf[s & 1][dir][b][0];
            for (int k = k0; k < k0 + 64; k += 4) {
                float4 v = *(const float4*)&src[k];
                int kp = k >> 1;
                *(float2*)&ht[kp * WP + b * 2]       = make_float2(v.x, v.y);
                *(float2*)&ht[(kp + 1) * WP + b * 2] = make_float2(v.z, v.w);
            }
            __syncthreads();
        }
    }
}

// ----------------------------------------------------------------------------
// Launch
// ----------------------------------------------------------------------------
extern "C" void kernel_launch(void* const* d_in, const int* in_sizes, int n_in,
                              void* d_out, int out_size)
{
    (void)in_sizes; (void)n_in; (void)out_size;
    const float* x     = (const float*)d_in[0];
    const float* Wih_f = (const float*)d_in[1];
    const float* Whh_f = (const float*)d_in[2];
    const float* bih_f = (const float*)d_in[3];
    const float* bhh_f = (const float*)d_in[4];
    const float* Wih_b = (const float*)d_in[5];
    const float* Whh_b = (const float*)d_in[6];
    const float* bih_b = (const float*)d_in[7];
    const float* bhh_b = (const float*)d_in[8];
    float* out = (float*)d_out;

    static bool attr_set = false;
    if (!attr_set) {
        cudaFuncSetAttribute(lstm_scan_kernel,
                             cudaFuncAttributeMaxDynamicSharedMemorySize,
                             SMEM_FLOATS * (int)sizeof(float));
        attr_set = true;
    }

    dim3 ggrid(16, 128, 2);
    gemm_xg_kernel<<<ggrid, 256>>>(x, Wih_f, Wih_b, bih_f, bhh_f, bih_b, bhh_b);
    lstm_scan_kernel<<<NBLK, 256, SMEM_FLOATS * sizeof(float)>>>(Whh_f, Whh_b, out);
}